// round 3
// baseline (speedup 1.0000x reference)
#include <cuda_runtime.h>

#define WIN 11
#define PAD 5
#define TILE 32
#define IN_TILE 42   // TILE + 2*PAD
#define IMG_H 512
#define IMG_W 512
#define NTHREADS 256

// SSIM / loss constants
#define C1V 1.0e-4f          // (0.01*1)^2
#define C2V 9.0e-4f          // (0.03*1)^2
#define EPS2 1.0e-12f        // (1e-6)^2
#define A_CHARB 0.3f
#define A_SSIM  0.6f
// alpha_mse * 20 = 2.0 folded below

__device__ float g_w[WIN];

__global__ void init_weights_kernel() {
    if (threadIdx.x == 0) {
        float w[WIN];
        float s = 0.f;
        #pragma unroll
        for (int i = 0; i < WIN; i++) {
            float x = (float)(i - PAD);
            w[i] = expf(-0.5f * x * x / (1.5f * 1.5f));
            s += w[i];
        }
        #pragma unroll
        for (int i = 0; i < WIN; i++) g_w[i] = w[i] / s;
    }
}

__global__ __launch_bounds__(NTHREADS)
void ssim_loss_kernel(const float* __restrict__ pred,
                      const float* __restrict__ targ,
                      float* __restrict__ out) {
    __shared__ float s_x[IN_TILE][IN_TILE + 2];
    __shared__ float s_y[IN_TILE][IN_TILE + 2];
    __shared__ float s_h[5][IN_TILE][TILE + 1];

    const int tid = threadIdx.x;
    const int tile_x = blockIdx.x * TILE;
    const int tile_y = blockIdx.y * TILE;
    const int plane = blockIdx.z;

    const float* __restrict__ px = pred + (size_t)plane * IMG_H * IMG_W;
    const float* __restrict__ py = targ + (size_t)plane * IMG_H * IMG_W;
    float* __restrict__ po = out + (size_t)plane * IMG_H * IMG_W;

    float w[WIN];
    #pragma unroll
    for (int i = 0; i < WIN; i++) w[i] = g_w[i];

    // ---- load halo tiles (zero-padded outside image, matching conv zero pad) ----
    for (int idx = tid; idx < IN_TILE * IN_TILE; idx += NTHREADS) {
        int r = idx / IN_TILE, c = idx % IN_TILE;
        int gr = tile_y + r - PAD;
        int gc = tile_x + c - PAD;
        float xv = 0.f, yv = 0.f;
        if (gr >= 0 && gr < IMG_H && gc >= 0 && gc < IMG_W) {
            size_t off = (size_t)gr * IMG_W + gc;
            xv = px[off];
            yv = py[off];
        }
        s_x[r][c] = xv;
        s_y[r][c] = yv;
    }
    __syncthreads();

    // ---- horizontal blur of the 5 quantities: x, y, x*x, y*y, x*y ----
    for (int idx = tid; idx < IN_TILE * TILE; idx += NTHREADS) {
        int r = idx / TILE, c = idx % TILE;
        float hx = 0.f, hy = 0.f, hxx = 0.f, hyy = 0.f, hxy = 0.f;
        #pragma unroll
        for (int k = 0; k < WIN; k++) {
            float xv = s_x[r][c + k];
            float yv = s_y[r][c + k];
            float wx = w[k] * xv;
            float wy = w[k] * yv;
            hx += wx;
            hy += wy;
            hxx = fmaf(wx, xv, hxx);
            hyy = fmaf(wy, yv, hyy);
            hxy = fmaf(wx, yv, hxy);
        }
        s_h[0][r][c] = hx;
        s_h[1][r][c] = hy;
        s_h[2][r][c] = hxx;
        s_h[3][r][c] = hyy;
        s_h[4][r][c] = hxy;
    }
    __syncthreads();

    // ---- vertical blur: each thread owns 4 consecutive output rows of one column ----
    const int c = tid & (TILE - 1);
    const int r0 = (tid >> 5) * 4;     // 0,4,...,28

    float acc[5][4];
    #pragma unroll
    for (int q = 0; q < 5; q++)
        #pragma unroll
        for (int j = 0; j < 4; j++) acc[q][j] = 0.f;

    #pragma unroll
    for (int k = 0; k < WIN + 3; k++) {        // rows r0 .. r0+13 feed the 4 outputs
        float v0 = s_h[0][r0 + k][c];
        float v1 = s_h[1][r0 + k][c];
        float v2 = s_h[2][r0 + k][c];
        float v3 = s_h[3][r0 + k][c];
        float v4 = s_h[4][r0 + k][c];
        #pragma unroll
        for (int j = 0; j < 4; j++) {
            int kk = k - j;
            if (kk >= 0 && kk < WIN) {
                float wk = w[kk];
                acc[0][j] = fmaf(wk, v0, acc[0][j]);
                acc[1][j] = fmaf(wk, v1, acc[1][j]);
                acc[2][j] = fmaf(wk, v2, acc[2][j]);
                acc[3][j] = fmaf(wk, v3, acc[3][j]);
                acc[4][j] = fmaf(wk, v4, acc[4][j]);
            }
        }
    }

    // ---- elementwise SSIM + Charbonnier + MSE combine ----
    #pragma unroll
    for (int j = 0; j < 4; j++) {
        float mu_x = acc[0][j];
        float mu_y = acc[1][j];
        float ex2  = acc[2][j];
        float ey2  = acc[3][j];
        float exy  = acc[4][j];

        float mxy = mu_x * mu_y;
        float s2x = ex2 - mu_x * mu_x;
        float s2y = ey2 - mu_y * mu_y;
        float sxy = exy - mxy;

        float A1 = 2.f * mxy + C1V;
        float A2 = 2.f * sxy + C2V;
        float B1 = mu_x * mu_x + mu_y * mu_y + C1V;
        float B2 = s2x + s2y + C2V;
        float ssim = __fdividef(A1, B1) * __fdividef(A2, B2);

        float xv = s_x[r0 + j + PAD][c + PAD];
        float yv = s_y[r0 + j + PAD][c + PAD];
        float d = xv - yv;
        float charb = sqrtf(fmaf(d, d, EPS2));

        float res = A_CHARB * charb + 2.0f * (d * d) + A_SSIM * (1.f - ssim);

        po[(size_t)(tile_y + r0 + j) * IMG_W + (tile_x + c)] = res;
    }
}

extern "C" void kernel_launch(void* const* d_in, const int* in_sizes, int n_in,
                              void* d_out, int out_size) {
    const float* pred = (const float*)d_in[0];
    const float* targ = (const float*)d_in[1];
    float* out = (float*)d_out;

    int planes = in_sizes[0] / (IMG_H * IMG_W);   // 16*3 = 48

    init_weights_kernel<<<1, 32>>>();
    dim3 grid(IMG_W / TILE, IMG_H / TILE, planes);
    ssim_loss_kernel<<<grid, NTHREADS>>>(pred, targ, out);
}